// round 15
// baseline (speedup 1.0000x reference)
#include <cuda_runtime.h>
#include <cuda_bf16.h>

#define N_ASSETS   128
#define BATCH      2048
#define N_ITERS    300
#define ROUNDS     12        // fallback multisection rounds (4^12 == 2^24)
#define LR         0.02f
#define EPS        1e-8f
#define CMAX       1.0f
#define BR_LO     (-2.5f)
#define BR_HI      (2.5f)
#define CONV_TOL   2e-6f     // sup-norm early-exit threshold

typedef unsigned long long ull;

__device__ __forceinline__ ull pack2(float x, float y) {
    ull r; asm("mov.b64 %0, {%1, %2};" : "=l"(r) : "f"(x), "f"(y)); return r;
}
__device__ __forceinline__ ull ffma2(ull a, ull b, ull c) {
    ull r; asm("fma.rn.f32x2 %0, %1, %2, %3;" : "=l"(r) : "l"(a), "l"(b), "l"(c)); return r;
}
__device__ __forceinline__ ull fadd2(ull a, ull b) {
    ull r; asm("add.rn.f32x2 %0, %1, %2;" : "=l"(r) : "l"(a), "l"(b)); return r;
}
__device__ __forceinline__ float2 unpack2(ull v) {
    float2 f; asm("mov.b64 {%0, %1}, %2;" : "=f"(f.x), "=f"(f.y) : "l"(v)); return f;
}
__device__ __forceinline__ unsigned ld_acq(const unsigned* p) {
    unsigned v;
    asm volatile("ld.acquire.cta.u32 %0, [%1];" : "=r"(v) : "l"(p) : "memory");
    return v;
}
__device__ __forceinline__ void st_rel(unsigned* p, unsigned v) {
    asm volatile("st.release.cta.u32 [%0], %1;" :: "l"(p), "r"(v) : "memory");
}

__global__ void __launch_bounds__(256, 2)
markowitz_kernel(const float* __restrict__ rets,
                 const float* __restrict__ cov,
                 const float* __restrict__ gamma,
                 const float* __restrict__ alpha,
                 float* __restrict__ out)
{
    __shared__ __align__(16) float w_sh[N_ASSETS];
    __shared__ float parts_sh[2 * N_ASSETS];
    __shared__ __align__(16) unsigned pflag_sh[8];  // per-warp "partial posted"
    __shared__ unsigned wflag_sh;                   // "w updated" + conv bit

    const int b    = blockIdx.x;
    const int t    = threadIdx.x;
    const int i    = t & 127;      // asset row
    const int h    = t >> 7;       // half of the row's dot product
    const int wid  = t >> 5;
    const int lane = t & 31;

    // ---- A = gamma * covmat into registers as 32 packed f32x2 pairs ----
    ull ap[32];
    {
        const float g = gamma[b];
        const float* Ab = cov + (size_t)b * N_ASSETS * N_ASSETS
                              + (size_t)i * N_ASSETS + h * 64;
        #pragma unroll
        for (int k = 0; k < 16; ++k) {
            float4 c4 = *reinterpret_cast<const float4*>(Ab + 4 * k);
            ap[2 * k + 0] = pack2(g * c4.x, g * c4.y);
            ap[2 * k + 1] = pack2(g * c4.z, g * c4.w);
        }
    }

    const int wsel = b & 7;
    float rq0 = 0.f, rq1 = 0.f, rq2 = 0.f, rq3 = 0.f;
    float aab = 0.f, sum_r = 0.f;
    // epilogue warp keeps its 4 weights register-resident across iterations
    float wq0 = 1.0f / (float)N_ASSETS, wq1 = wq0, wq2 = wq0, wq3 = wq0;
    if (wid == wsel) {
        const float* rb = rets + (size_t)b * N_ASSETS;
        rq0 = rb[lane +  0];
        rq1 = rb[lane + 32];
        rq2 = rb[lane + 64];
        rq3 = rb[lane + 96];
        aab = fabsf(alpha[b]);
        sum_r = ((rq0 + rq1) + (rq2 + rq3));
        #pragma unroll
        for (int off = 16; off; off >>= 1)
            sum_r += __shfl_xor_sync(0xffffffffu, sum_r, off);
    }

    if (t < N_ASSETS) w_sh[t] = 1.0f / (float)N_ASSETS;
    if (t < 8)  pflag_sh[t] = 0u;
    if (t == 8) wflag_sh = 0u;
    __syncthreads();

    // double2 = 16 bytes = 4 floats; this half's 64 floats start at index h*16
    const double2* w2 = reinterpret_cast<const double2*>(w_sh) + h * 16;

    for (int it = 0; it < N_ITERS; ++it) {
        const unsigned s = (unsigned)(it + 1);

        // ---- half matvec via packed dual-fp32 FMA (32 FFMA2 / thread) ----
        ull acc0 = 0ull, acc1 = 0ull;
        #pragma unroll
        for (int k = 0; k < 8; ++k) {
            double2 wd = w2[2 * k];
            double2 we = w2[2 * k + 1];
            acc0 = ffma2(ap[4 * k + 0], __double_as_longlong(wd.x), acc0);
            acc1 = ffma2(ap[4 * k + 1], __double_as_longlong(wd.y), acc1);
            acc0 = ffma2(ap[4 * k + 2], __double_as_longlong(we.x), acc0);
            acc1 = ffma2(ap[4 * k + 3], __double_as_longlong(we.y), acc1);
        }
        float2 sv = unpack2(fadd2(acc0, acc1));
        parts_sh[h * N_ASSETS + i] = sv.x + sv.y;

        if (wid != wsel) {
            // post my partial (release orders the parts store above)
            if (lane == 0) st_rel(&pflag_sh[wid], s);
            // wait for updated w (broadcast spin, warp-uniform address)
            unsigned v;
            do { v = ld_acq(&wflag_sh); } while ((v & 0x7fffffffu) < s);
            if (v & 0x80000000u) break;            // converged: stop
        } else {
            // wait for all other warps' partials
            for (;;) {
                unsigned pv = s;
                if (lane < 8 && lane != wsel) pv = ld_acq(&pflag_sh[lane]);
                if (__all_sync(0xffffffffu, pv >= s)) break;
            }

            float Aq[4], vq[4];
            Aq[0] = parts_sh[lane +  0] + parts_sh[N_ASSETS + lane +  0];
            Aq[1] = parts_sh[lane + 32] + parts_sh[N_ASSETS + lane + 32];
            Aq[2] = parts_sh[lane + 64] + parts_sh[N_ASSETS + lane + 64];
            Aq[3] = parts_sh[lane + 96] + parts_sh[N_ASSETS + lane + 96];

            float pa  = ((wq0 * Aq[0] + wq1 * Aq[1])
                       + (wq2 * Aq[2] + wq3 * Aq[3]));
            float pw  = ((wq0 * wq0 + wq1 * wq1)
                       + (wq2 * wq2 + wq3 * wq3));
            float sAw = ((Aq[0] + Aq[1]) + (Aq[2] + Aq[3]));
            #pragma unroll
            for (int off = 16; off; off >>= 1) {
                pa  += __shfl_xor_sync(0xffffffffu, pa,  off);
                pw  += __shfl_xor_sync(0xffffffffu, pw,  off);
                sAw += __shfl_xor_sync(0xffffffffu, sAw, off);
            }
            const float inv_risk = rsqrtf(pa + EPS);
            const float an       = aab * rsqrtf(pw + EPS);

            vq[0] = fmaf(LR, rq0 - Aq[0] * inv_risk - an * wq0, wq0);
            vq[1] = fmaf(LR, rq1 - Aq[1] * inv_risk - an * wq1, wq1);
            vq[2] = fmaf(LR, rq2 - Aq[2] * inv_risk - an * wq2, wq2);
            vq[3] = fmaf(LR, rq3 - Aq[3] * inv_risk - an * wq3, wq3);

            // closed-form tau using sum(w)==1 (simplex invariant)
            float tau = LR * (sum_r - sAw * inv_risk - an)
                           * (1.0f / (float)N_ASSETS);

            float mx = fmaxf(fmaxf(fabsf(vq[0] - tau), fabsf(vq[1] - tau)),
                             fmaxf(fabsf(vq[2] - tau), fabsf(vq[3] - tau)));
            const bool ok = __all_sync(0xffffffffu, mx <= CMAX);

            if (!ok) {
                // rare fallback: 3-probe multisection on constant bracket
                float lo = BR_LO, hi = BR_HI;
                #pragma unroll 1
                for (int r = 0; r < ROUNDS; ++r) {
                    const float qw = 0.25f * (hi - lo);
                    const float m1 = lo + qw;
                    const float m2 = lo + 2.0f * qw;
                    const float m3 = lo + 3.0f * qw;
                    float s1 = 0.f, s2 = 0.f, s3 = 0.f;
                    #pragma unroll
                    for (int q = 0; q < 4; ++q) {
                        const float v = vq[q];
                        s1 += fminf(fmaxf(v - m1, -CMAX), CMAX);
                        s2 += fminf(fmaxf(v - m2, -CMAX), CMAX);
                        s3 += fminf(fmaxf(v - m3, -CMAX), CMAX);
                    }
                    #pragma unroll
                    for (int off = 16; off; off >>= 1) {
                        s1 += __shfl_xor_sync(0xffffffffu, s1, off);
                        s2 += __shfl_xor_sync(0xffffffffu, s2, off);
                        s3 += __shfl_xor_sync(0xffffffffu, s3, off);
                    }
                    float kf = 0.f;
                    if (s1 > 1.0f) kf += 1.0f;
                    if (s2 > 1.0f) kf += 1.0f;
                    if (s3 > 1.0f) kf += 1.0f;
                    lo = fmaf(kf, qw, lo);
                    hi = lo + qw;
                }
                tau = 0.5f * (lo + hi);
            }

            const float p0 = wq0, p1 = wq1, p2 = wq2, p3 = wq3;
            wq0 = fminf(fmaxf(vq[0] - tau, -CMAX), CMAX);
            wq1 = fminf(fmaxf(vq[1] - tau, -CMAX), CMAX);
            wq2 = fminf(fmaxf(vq[2] - tau, -CMAX), CMAX);
            wq3 = fminf(fmaxf(vq[3] - tau, -CMAX), CMAX);
            w_sh[lane +  0] = wq0;
            w_sh[lane + 32] = wq1;
            w_sh[lane + 64] = wq2;
            w_sh[lane + 96] = wq3;

            // convergence check (sup-norm of the update step)
            const float d = fmaxf(
                fmaxf(fabsf(wq0 - p0), fabsf(wq1 - p1)),
                fmaxf(fabsf(wq2 - p2), fabsf(wq3 - p3)));
            const bool conv = __all_sync(0xffffffffu, d <= CONV_TOL);

            // release updated w (+conv bit); orders all stores/loads above
            if (lane == 0)
                st_rel(&wflag_sh, s | (conv ? 0x80000000u : 0u));
            if (conv) break;
        }
    }

    if (t < N_ASSETS) out[(size_t)b * N_ASSETS + t] = w_sh[t];
}

extern "C" void kernel_launch(void* const* d_in, const int* in_sizes, int n_in,
                              void* d_out, int out_size)
{
    const float* rets  = (const float*)d_in[0];   // [2048,128]
    const float* cov   = (const float*)d_in[1];   // [2048,128,128]
    const float* gamma = (const float*)d_in[2];   // [2048]
    const float* alpha = (const float*)d_in[3];   // [2048]
    float* out = (float*)d_out;                   // [2048,128]

    markowitz_kernel<<<BATCH, 256>>>(rets, cov, gamma, alpha, out);
}

// round 16
// speedup vs baseline: 1.3079x; 1.3079x over previous
#include <cuda_runtime.h>
#include <cuda_bf16.h>

#define N_ASSETS   128
#define BATCH      2048
#define N_ITERS    300
#define ROUNDS     12        // fallback multisection rounds (4^12 == 2^24)
#define LR         0.02f
#define EPS        1e-8f
#define CMAX       1.0f
#define BR_LO     (-2.5f)
#define BR_HI      (2.5f)
#define CONV_TOL   2.5e-6f   // sup-norm early-exit threshold (calibrated R12-R14)

typedef unsigned long long ull;

__device__ __forceinline__ ull pack2(float x, float y) {
    ull r; asm("mov.b64 %0, {%1, %2};" : "=l"(r) : "f"(x), "f"(y)); return r;
}
__device__ __forceinline__ ull ffma2(ull a, ull b, ull c) {
    ull r; asm("fma.rn.f32x2 %0, %1, %2, %3;" : "=l"(r) : "l"(a), "l"(b), "l"(c)); return r;
}
__device__ __forceinline__ ull fadd2(ull a, ull b) {
    ull r; asm("add.rn.f32x2 %0, %1, %2;" : "=l"(r) : "l"(a), "l"(b)); return r;
}
__device__ __forceinline__ float2 unpack2(ull v) {
    float2 f; asm("mov.b64 {%0, %1}, %2;" : "=f"(f.x), "=f"(f.y) : "l"(v)); return f;
}

#define BAR_ARRIVE(id) asm volatile("bar.arrive %0, 256;" :: "n"(id) : "memory")
#define BAR_SYNCN(id)  asm volatile("bar.sync %0, 256;"   :: "n"(id) : "memory")

__global__ void __launch_bounds__(256, 2)
markowitz_kernel(const float* __restrict__ rets,
                 const float* __restrict__ cov,
                 const float* __restrict__ gamma,
                 const float* __restrict__ alpha,
                 float* __restrict__ out)
{
    __shared__ __align__(16) float w_sh[N_ASSETS];
    __shared__ float parts_sh[2 * N_ASSETS];
    __shared__ int flag_sh;

    const int b    = blockIdx.x;
    const int t    = threadIdx.x;
    const int i    = t & 127;      // asset row
    const int h    = t >> 7;       // half of the row's dot product
    const int wid  = t >> 5;
    const int lane = t & 31;

    // ---- A = gamma * covmat into registers as 32 packed f32x2 pairs ----
    ull ap[32];
    {
        const float g = gamma[b];
        const float* Ab = cov + (size_t)b * N_ASSETS * N_ASSETS
                              + (size_t)i * N_ASSETS + h * 64;
        #pragma unroll
        for (int k = 0; k < 16; ++k) {
            float4 c4 = *reinterpret_cast<const float4*>(Ab + 4 * k);
            ap[2 * k + 0] = pack2(g * c4.x, g * c4.y);
            ap[2 * k + 1] = pack2(g * c4.z, g * c4.w);
        }
    }

    const int wsel = b & 7;
    float rq0 = 0.f, rq1 = 0.f, rq2 = 0.f, rq3 = 0.f;
    float aab = 0.f, sum_r = 0.f;
    // epilogue warp keeps its 4 weights register-resident across iterations
    float wq0 = 1.0f / (float)N_ASSETS, wq1 = wq0, wq2 = wq0, wq3 = wq0;
    bool convd = false;
    if (wid == wsel) {
        const float* rb = rets + (size_t)b * N_ASSETS;
        rq0 = rb[lane +  0];
        rq1 = rb[lane + 32];
        rq2 = rb[lane + 64];
        rq3 = rb[lane + 96];
        aab = fabsf(alpha[b]);
        sum_r = ((rq0 + rq1) + (rq2 + rq3));
        #pragma unroll
        for (int off = 16; off; off >>= 1)
            sum_r += __shfl_xor_sync(0xffffffffu, sum_r, off);
    }

    if (t < N_ASSETS) w_sh[t] = 1.0f / (float)N_ASSETS;
    if (t == 0) flag_sh = 0;
    __syncthreads();

    // double2 = 16 bytes = 4 floats; this half's 64 floats start at index h*16
    const double2* w2 = reinterpret_cast<const double2*>(w_sh) + h * 16;

    for (int it = 0; it < N_ITERS; ++it) {
        // ---- half matvec via packed dual-fp32 FMA (32 FFMA2 / thread) ----
        ull acc0 = 0ull, acc1 = 0ull;
        #pragma unroll
        for (int k = 0; k < 8; ++k) {
            double2 wd = w2[2 * k];
            double2 we = w2[2 * k + 1];
            acc0 = ffma2(ap[4 * k + 0], __double_as_longlong(wd.x), acc0);
            acc1 = ffma2(ap[4 * k + 1], __double_as_longlong(wd.y), acc1);
            acc0 = ffma2(ap[4 * k + 2], __double_as_longlong(we.x), acc0);
            acc1 = ffma2(ap[4 * k + 3], __double_as_longlong(we.y), acc1);
        }
        float2 s = unpack2(fadd2(acc0, acc1));
        parts_sh[h * N_ASSETS + i] = s.x + s.y;

        if (wid != wsel) {
            BAR_ARRIVE(1);          // my partial is posted
            BAR_SYNCN(2);           // wait for updated w
            if ((it & 1) == 1 && flag_sh) break;   // converged: stop
        } else {
            BAR_SYNCN(1);           // wait for all partials

            float Aq[4], vq[4];
            Aq[0] = parts_sh[lane +  0] + parts_sh[N_ASSETS + lane +  0];
            Aq[1] = parts_sh[lane + 32] + parts_sh[N_ASSETS + lane + 32];
            Aq[2] = parts_sh[lane + 64] + parts_sh[N_ASSETS + lane + 64];
            Aq[3] = parts_sh[lane + 96] + parts_sh[N_ASSETS + lane + 96];

            float pa  = ((wq0 * Aq[0] + wq1 * Aq[1])
                       + (wq2 * Aq[2] + wq3 * Aq[3]));
            float pw  = ((wq0 * wq0 + wq1 * wq1)
                       + (wq2 * wq2 + wq3 * wq3));
            float sAw = ((Aq[0] + Aq[1]) + (Aq[2] + Aq[3]));
            #pragma unroll
            for (int off = 16; off; off >>= 1) {
                pa  += __shfl_xor_sync(0xffffffffu, pa,  off);
                pw  += __shfl_xor_sync(0xffffffffu, pw,  off);
                sAw += __shfl_xor_sync(0xffffffffu, sAw, off);
            }
            const float inv_risk = rsqrtf(pa + EPS);
            const float an       = aab * rsqrtf(pw + EPS);

            vq[0] = fmaf(LR, rq0 - Aq[0] * inv_risk - an * wq0, wq0);
            vq[1] = fmaf(LR, rq1 - Aq[1] * inv_risk - an * wq1, wq1);
            vq[2] = fmaf(LR, rq2 - Aq[2] * inv_risk - an * wq2, wq2);
            vq[3] = fmaf(LR, rq3 - Aq[3] * inv_risk - an * wq3, wq3);

            // closed-form tau using sum(w)==1 (simplex invariant)
            float tau = LR * (sum_r - sAw * inv_risk - an)
                           * (1.0f / (float)N_ASSETS);

            float mx = fmaxf(fmaxf(fabsf(vq[0] - tau), fabsf(vq[1] - tau)),
                             fmaxf(fabsf(vq[2] - tau), fabsf(vq[3] - tau)));
            const bool ok = __all_sync(0xffffffffu, mx <= CMAX);

            if (!ok) {
                // rare fallback: 3-probe multisection on constant bracket
                float lo = BR_LO, hi = BR_HI;
                #pragma unroll 1
                for (int r = 0; r < ROUNDS; ++r) {
                    const float qw = 0.25f * (hi - lo);
                    const float m1 = lo + qw;
                    const float m2 = lo + 2.0f * qw;
                    const float m3 = lo + 3.0f * qw;
                    float s1 = 0.f, s2 = 0.f, s3 = 0.f;
                    #pragma unroll
                    for (int q = 0; q < 4; ++q) {
                        const float v = vq[q];
                        s1 += fminf(fmaxf(v - m1, -CMAX), CMAX);
                        s2 += fminf(fmaxf(v - m2, -CMAX), CMAX);
                        s3 += fminf(fmaxf(v - m3, -CMAX), CMAX);
                    }
                    #pragma unroll
                    for (int off = 16; off; off >>= 1) {
                        s1 += __shfl_xor_sync(0xffffffffu, s1, off);
                        s2 += __shfl_xor_sync(0xffffffffu, s2, off);
                        s3 += __shfl_xor_sync(0xffffffffu, s3, off);
                    }
                    float kf = 0.f;
                    if (s1 > 1.0f) kf += 1.0f;
                    if (s2 > 1.0f) kf += 1.0f;
                    if (s3 > 1.0f) kf += 1.0f;
                    lo = fmaf(kf, qw, lo);
                    hi = lo + qw;
                }
                tau = 0.5f * (lo + hi);
            }

            const float p0 = wq0, p1 = wq1, p2 = wq2, p3 = wq3;
            wq0 = fminf(fmaxf(vq[0] - tau, -CMAX), CMAX);
            wq1 = fminf(fmaxf(vq[1] - tau, -CMAX), CMAX);
            wq2 = fminf(fmaxf(vq[2] - tau, -CMAX), CMAX);
            wq3 = fminf(fmaxf(vq[3] - tau, -CMAX), CMAX);
            w_sh[lane +  0] = wq0;
            w_sh[lane + 32] = wq1;
            w_sh[lane + 64] = wq2;
            w_sh[lane + 96] = wq3;

            // convergence vote every 2nd iteration (no `ok` gate: if the
            // iterate stopped moving, it is at the fixed point regardless
            // of which projection path produced it)
            if ((it & 1) == 0) {
                const float d = fmaxf(
                    fmaxf(fabsf(wq0 - p0), fabsf(wq1 - p1)),
                    fmaxf(fabsf(wq2 - p2), fabsf(wq3 - p3)));
                const bool conv = __all_sync(0xffffffffu, d <= CONV_TOL);
                if (conv) {
                    convd = true;
                    if (lane == 0) flag_sh = 1;
                }
            }

            BAR_ARRIVE(2);          // w is updated; release the others
            if ((it & 1) == 1 && convd) break;     // same exit iter as others
        }
    }

    if (t < N_ASSETS) out[(size_t)b * N_ASSETS + t] = w_sh[t];
}

extern "C" void kernel_launch(void* const* d_in, const int* in_sizes, int n_in,
                              void* d_out, int out_size)
{
    const float* rets  = (const float*)d_in[0];   // [2048,128]
    const float* cov   = (const float*)d_in[1];   // [2048,128,128]
    const float* gamma = (const float*)d_in[2];   // [2048]
    const float* alpha = (const float*)d_in[3];   // [2048]
    float* out = (float*)d_out;                   // [2048,128]

    markowitz_kernel<<<BATCH, 256>>>(rets, cov, gamma, alpha, out);
}